// round 1
// baseline (speedup 1.0000x reference)
#include <cuda_runtime.h>
#include <cuda_bf16.h>

#define N_NODES 50000
#define E_CAP   700000
#define HEADS   4
#define OUT_CH  16
#define OUT_NEU 32
#define IN_CH   128
#define HID     128   // HEADS*OUT_NEU

// ---- output layout (flat concat of reference return tuple, fp32) ----
#define OFF_OUT    0
#define OFF_IXZ    (N_NODES * 64)                  // 3,200,000
#define OFF_SCALAR (OFF_IXZ + N_NODES)             // 3,250,000
#define OFF_MEAN   (OFF_SCALAR + 1)                // 3,250,001
#define OFF_STD    (OFF_MEAN + N_NODES * 64)       // 6,450,001

// ---- scratch (device globals; no allocation allowed) ----
__device__ __align__(16) float    g_h[N_NODES * HID];      // node features after GEMM
__device__ __align__(16) float    g_agg[N_NODES * HID];    // segment-sum accumulator
__device__ __align__(16) float    g_aI[N_NODES * HEADS];   // h . att_i  (dst term)
__device__ __align__(16) float    g_aJ[N_NODES * HEADS];   // h . att_j  (src term)
__device__ __align__(16) unsigned g_m[N_NODES * HEADS];    // ordered-uint encoded max
__device__ __align__(16) float    g_denom[N_NODES * HEADS];
__device__ float4 g_e[E_CAP];                              // per-edge alpha, then exp

// monotonic float<->uint encoding for atomicMax on floats
__device__ __forceinline__ unsigned enc_f(float f) {
    unsigned b = __float_as_uint(f);
    return (b & 0x80000000u) ? ~b : (b | 0x80000000u);
}
__device__ __forceinline__ float dec_f(unsigned u) {
    return (u & 0x80000000u) ? __uint_as_float(u ^ 0x80000000u)
                             : __uint_as_float(~u);
}

__device__ __forceinline__ void red_add_v4(float* gptr, float a, float b, float c, float d) {
    asm volatile("red.global.add.v4.f32 [%0], {%1, %2, %3, %4};"
                 :: "l"(gptr), "f"(a), "f"(b), "f"(c), "f"(d) : "memory");
}

// ---------------------------------------------------------------- K0: init
__global__ void init_kernel() {
    int i = blockIdx.x * blockDim.x + threadIdx.x;
    int stride = gridDim.x * blockDim.x;
    for (int k = i; k < N_NODES * HID; k += stride) g_agg[k] = 0.0f;
    for (int k = i; k < N_NODES * HEADS; k += stride) {
        g_m[k] = 0u;          // < enc(-inf) is impossible; enc of any finite f > 0
        g_denom[k] = 0.0f;
    }
}

// ------------------------------------------- K1: GEMM + per-node attention dots
// 16 rows per block, 256 threads: col = tid&127, row-half = tid>>7 (8 rows each).
// smem: W[128][128] (64KB) + X^T[128][20-padded] (10KB)
#define GEMM_ROWS 16
#define XT_PITCH  20
#define GEMM_SMEM ((IN_CH * HID + IN_CH * XT_PITCH) * 4)

__global__ __launch_bounds__(256) void gemm_kernel(
    const float* __restrict__ x, const float* __restrict__ w,
    const float* __restrict__ att)
{
    extern __shared__ float sm[];
    float* sW  = sm;                 // [k][col]
    float* sXT = sm + IN_CH * HID;   // [k][row] pitch 20

    const int tid  = threadIdx.x;
    const int row0 = blockIdx.x * GEMM_ROWS;

    for (int i = tid; i < IN_CH * HID; i += 256) sW[i] = w[i];
    for (int i = tid; i < GEMM_ROWS * IN_CH; i += 256) {
        int r = i >> 7, k = i & 127;
        sXT[k * XT_PITCH + r] = x[(row0 + r) * IN_CH + k];
    }
    __syncthreads();

    const int col = tid & 127;
    const int rh  = tid >> 7;      // 0 or 1

    float acc[8];
#pragma unroll
    for (int j = 0; j < 8; j++) acc[j] = 0.0f;

#pragma unroll 4
    for (int k = 0; k < IN_CH; k++) {
        const float wv = sW[k * HID + col];
        const float4 a0 = *(const float4*)&sXT[k * XT_PITCH + rh * 8];
        const float4 a1 = *(const float4*)&sXT[k * XT_PITCH + rh * 8 + 4];
        acc[0] = fmaf(a0.x, wv, acc[0]);
        acc[1] = fmaf(a0.y, wv, acc[1]);
        acc[2] = fmaf(a0.z, wv, acc[2]);
        acc[3] = fmaf(a0.w, wv, acc[3]);
        acc[4] = fmaf(a1.x, wv, acc[4]);
        acc[5] = fmaf(a1.y, wv, acc[5]);
        acc[6] = fmaf(a1.z, wv, acc[6]);
        acc[7] = fmaf(a1.w, wv, acc[7]);
    }

    // each warp covers exactly one head's 32 neurons (col bits guarantee this)
    const int head = col >> 5;
    const int lane = col & 31;
    const float attI = att[head * 64 + lane];
    const float attJ = att[head * 64 + 32 + lane];

#pragma unroll
    for (int j = 0; j < 8; j++) {
        const int row = row0 + rh * 8 + j;
        g_h[row * HID + col] = acc[j];
        float sI = acc[j] * attI;
        float sJ = acc[j] * attJ;
#pragma unroll
        for (int o = 16; o; o >>= 1) {
            sI += __shfl_xor_sync(0xffffffffu, sI, o);
            sJ += __shfl_xor_sync(0xffffffffu, sJ, o);
        }
        if (lane == 0) {
            g_aI[row * HEADS + head] = sI;
            g_aJ[row * HEADS + head] = sJ;
        }
    }
}

// ----------------------------------- K2: per-edge alpha + leaky-relu + segment max
__global__ void edge_alpha_max(const int* __restrict__ src,
                               const int* __restrict__ dst, int E)
{
    int e = blockIdx.x * blockDim.x + threadIdx.x;
    if (e >= E) return;
    int s = src[e], d = dst[e];
    const float4 ai = *(const float4*)&g_aI[d * 4];
    const float4 aj = *(const float4*)&g_aJ[s * 4];
    float4 al;
    al.x = ai.x + aj.x; al.y = ai.y + aj.y;
    al.z = ai.z + aj.z; al.w = ai.w + aj.w;
    al.x = al.x > 0.0f ? al.x : 0.2f * al.x;
    al.y = al.y > 0.0f ? al.y : 0.2f * al.y;
    al.z = al.z > 0.0f ? al.z : 0.2f * al.z;
    al.w = al.w > 0.0f ? al.w : 0.2f * al.w;
    g_e[e] = al;
    atomicMax(&g_m[d * 4 + 0], enc_f(al.x));
    atomicMax(&g_m[d * 4 + 1], enc_f(al.y));
    atomicMax(&g_m[d * 4 + 2], enc_f(al.z));
    atomicMax(&g_m[d * 4 + 3], enc_f(al.w));
}

// ----------------------------------- K3: e = exp(alpha - m[dst]); denom += e
__global__ void edge_exp_sum(const int* __restrict__ dst, int E)
{
    int e = blockIdx.x * blockDim.x + threadIdx.x;
    if (e >= E) return;
    int d = dst[e];
    float4 al = g_e[e];
    uint4 mu = *(const uint4*)&g_m[d * 4];
    float4 ev;
    ev.x = expf(al.x - dec_f(mu.x));
    ev.y = expf(al.y - dec_f(mu.y));
    ev.z = expf(al.z - dec_f(mu.z));
    ev.w = expf(al.w - dec_f(mu.w));
    g_e[e] = ev;
    red_add_v4(&g_denom[d * 4], ev.x, ev.y, ev.z, ev.w);
}

// ----------------------------------- K4: agg[dst] += h[src] * e/(denom+eps)
// 32 threads per edge; lane -> (head = lane>>3, float4-chunk = lane&7)
__global__ void edge_agg(const int* __restrict__ src,
                         const int* __restrict__ dst, int E)
{
    int g = blockIdx.x * blockDim.x + threadIdx.x;
    int e = g >> 5;
    if (e >= E) return;
    int lane = g & 31;
    int s = src[e], d = dst[e];
    int head = lane >> 3;
    float ev  = ((const float*)g_e)[e * 4 + head];
    float den = g_denom[d * 4 + head];
    float coef = ev / (den + 1e-16f);
    float4 hv = ((const float4*)g_h)[s * 32 + lane];  // lane*4 == head*32 + q*4
    red_add_v4(&g_agg[d * HID + lane * 4],
               hv.x * coef, hv.y * coef, hv.z * coef, hv.w * coef);
}

// ----------------------------------- K5: VIB epilogue + all outputs
// warp per node: lane -> (head = lane>>3, cc = lane&7 handles c=cc and c=cc+8)
__global__ __launch_bounds__(256) void finalize_kernel(
    const float* __restrict__ bias, float* __restrict__ out)
{
    int warp = threadIdx.x >> 5, lane = threadIdx.x & 31;
    int n = blockIdx.x * 8 + warp;
    if (n >= N_NODES) return;
    int head = lane >> 3, cc = lane & 7;

    float kl = 0.0f;
#pragma unroll
    for (int t = 0; t < 2; t++) {
        int c = cc + t * 8;
        float mv = g_agg[n * HID + head * 32 + c] + bias[head * 32 + c];
        float sp = g_agg[n * HID + head * 32 + 16 + c] + bias[head * 32 + 16 + c] - 5.0f;
        // stable softplus: max(x,0) + log1p(exp(-|x|))
        float st = fmaxf(sp, 0.0f) + log1pf(expf(-fabsf(sp))) + 1e-10f;
        kl += -logf(st) + 0.5f * (st * st + mv * mv) - 0.5f;
        out[OFF_OUT  + n * 64 + head * 16 + c] = mv;
        out[OFF_MEAN + (n * 4 + head) * 16 + c] = mv;
        out[OFF_STD  + (n * 4 + head) * 16 + c] = st;
    }
#pragma unroll
    for (int o = 16; o; o >>= 1) kl += __shfl_xor_sync(0xffffffffu, kl, o);
    if (lane == 0) out[OFF_IXZ + n] = kl * 0.25f;
    if (blockIdx.x == 0 && threadIdx.x == 0) out[OFF_SCALAR] = 0.0f;
}

// ---------------------------------------------------------------- launch
extern "C" void kernel_launch(void* const* d_in, const int* in_sizes, int n_in,
                              void* d_out, int out_size)
{
    const float* x    = (const float*)d_in[0];
    const int*   ei   = (const int*)d_in[1];
    const float* w    = (const float*)d_in[2];
    const float* att  = (const float*)d_in[3];
    const float* bias = (const float*)d_in[4];
    float* out = (float*)d_out;

    const int E = in_sizes[1] / 2;
    const int* src = ei;
    const int* dst = ei + E;

    cudaFuncSetAttribute(gemm_kernel,
                         cudaFuncAttributeMaxDynamicSharedMemorySize, GEMM_SMEM);

    init_kernel<<<512, 256>>>();
    gemm_kernel<<<N_NODES / GEMM_ROWS, 256, GEMM_SMEM>>>(x, w, att);

    const int eb = (E + 255) / 256;
    edge_alpha_max<<<eb, 256>>>(src, dst, E);
    edge_exp_sum<<<eb, 256>>>(dst, E);
    edge_agg<<<(E * 32 + 255) / 256, 256>>>(src, dst, E);
    finalize_kernel<<<(N_NODES + 7) / 8, 256>>>(bias, out);
}